// round 6
// baseline (speedup 1.0000x reference)
#include <cuda_runtime.h>

#define N_IMG 4
#define C 19
#define HH 768
#define WW 768
#define HW (HH * WW)
#define NV (HW / 4)
#define IGNORE_LBL 255
#define MB 288   // blocks per image

// ---------------- device scratch (fully rewritten every call) ----------------
__device__ float g_ss[N_IMG][MB][C];   // per-block sum of lp, seg-valid pixels, by class
__device__ float g_cs[N_IMG][MB][C];   // per-block seg counts (== class histogram)
__device__ float g_as[N_IMG][MB][C];   // per-block sum of lp, att pixels, by class
__device__ float g_ca[N_IMG][MB][C];   // per-block att counts (== att histogram)
__device__ float g_sb[N_IMG][MB][4];   // per-block (pos_cnt, neg_cnt, bce_pos, bce_neg)

// ---------------- K1: single fused streaming pass ----------------
__global__ void __launch_bounds__(256) k_main(const float* __restrict__ segin,
                                              const float* __restrict__ edgein,
                                              const int* __restrict__ segmask,
                                              const int* __restrict__ edgemask) {
    __shared__ float sh_ss[8][C], sh_cs[8][C], sh_as[8][C], sh_ca[8][C];
    __shared__ float sh_sc4[8][4];

    const int n    = blockIdx.y;
    const int bx   = blockIdx.x;
    const int tid  = threadIdx.x;
    const int wrp  = tid >> 5;
    const int lane = tid & 31;

    for (int i = tid; i < 8 * C; i += 256) {
        ((float*)sh_ss)[i] = 0.f; ((float*)sh_cs)[i] = 0.f;
        ((float*)sh_as)[i] = 0.f; ((float*)sh_ca)[i] = 0.f;
    }
    __syncthreads();

    const float4* sb4 = (const float4*)(segin    + (size_t)n * C * HW);
    const float4* ei4 = (const float4*)(edgein   + (size_t)n * HW);
    const int4*   sm4 = (const int4*)(segmask   + (size_t)n * HW);
    const int4*   em4 = (const int4*)(edgemask  + (size_t)n * HW);

    float pc = 0.f, nc = 0.f, sp = 0.f, sn = 0.f;

    const int stride = 256 * MB;
    for (int p = bx * 256 + tid; p < NV; p += stride) {
        const int4   t4 = sm4[p];
        const float4 e4 = ei4[p];
        const int4   m4 = em4[p];

        const int v0 = (t4.x != IGNORE_LBL), v1 = (t4.y != IGNORE_LBL),
                  v2 = (t4.z != IGNORE_LBL), v3 = (t4.w != IGNORE_LBL);
        const int tc0 = min(max(t4.x, 0), C - 1), tc1 = min(max(t4.y, 0), C - 1),
                  tc2 = min(max(t4.z, 0), C - 1), tc3 = min(max(t4.w, 0), C - 1);

        // O(1) logits: exp overflow-safe without max subtraction
        float s0 = 0.f, s1 = 0.f, s2 = 0.f, s3 = 0.f;
        float xt0 = 0.f, xt1 = 0.f, xt2 = 0.f, xt3 = 0.f;
        #pragma unroll
        for (int c = 0; c < C; c++) {
            float4 v = sb4[(size_t)c * NV + p];
            s0 += __expf(v.x); xt0 = (c == tc0) ? v.x : xt0;
            s1 += __expf(v.y); xt1 = (c == tc1) ? v.y : xt1;
            s2 += __expf(v.z); xt2 = (c == tc2) ? v.z : xt2;
            s3 += __expf(v.w); xt3 = (c == tc3) ? v.w : xt3;
        }
        const float lp0 = xt0 - __logf(s0);
        const float lp1 = xt1 - __logf(s1);
        const float lp2 = xt2 - __logf(s2);
        const float lp3 = xt3 - __logf(s3);

        // per-class accumulation (per-warp bins) + BCE scalar accumulation
        #pragma unroll
        for (int j = 0; j < 4; j++) {
            const int   vv = (j == 0) ? v0  : (j == 1) ? v1  : (j == 2) ? v2  : v3;
            const int   tc = (j == 0) ? tc0 : (j == 1) ? tc1 : (j == 2) ? tc2 : tc3;
            const float lp = (j == 0) ? lp0 : (j == 1) ? lp1 : (j == 2) ? lp2 : lp3;
            const float e  = (j == 0) ? e4.x : (j == 1) ? e4.y : (j == 2) ? e4.z : e4.w;
            const int   m  = (j == 0) ? m4.x : (j == 1) ? m4.y : (j == 2) ? m4.z : m4.w;

            if (vv) {
                atomicAdd(&sh_ss[wrp][tc], lp);
                atomicAdd(&sh_cs[wrp][tc], 1.f);
                if (e > 0.8f) {
                    atomicAdd(&sh_as[wrp][tc], lp);
                    atomicAdd(&sh_ca[wrp][tc], 1.f);
                }
            }

            const float b = fmaxf(e, 0.f) + __logf(1.f + __expf(-fabsf(e)));
            sp += (m == 1) ? (b - e) : 0.f;
            sn += (m == 0) ? b : 0.f;
            pc += (m == 1);
            nc += (m == 0);
        }
    }

    // scalar warp reduce
    #pragma unroll
    for (int o = 16; o > 0; o >>= 1) {
        pc += __shfl_down_sync(0xffffffffu, pc, o);
        nc += __shfl_down_sync(0xffffffffu, nc, o);
        sp += __shfl_down_sync(0xffffffffu, sp, o);
        sn += __shfl_down_sync(0xffffffffu, sn, o);
    }
    if (lane == 0) { sh_sc4[wrp][0] = pc; sh_sc4[wrp][1] = nc; sh_sc4[wrp][2] = sp; sh_sc4[wrp][3] = sn; }
    __syncthreads();

    // combine 8 warp bins -> per-block partials
    if (tid < 2 * C) {
        const int c    = tid % C;
        const int kind = tid / C;
        float s = 0.f, cnt = 0.f;
        #pragma unroll
        for (int w = 0; w < 8; w++) {
            s   += kind ? sh_as[w][c] : sh_ss[w][c];
            cnt += kind ? sh_ca[w][c] : sh_cs[w][c];
        }
        if (kind) { g_as[n][bx][c] = s; g_ca[n][bx][c] = cnt; }
        else      { g_ss[n][bx][c] = s; g_cs[n][bx][c] = cnt; }
    }
    if (tid >= 40 && tid < 44) {
        const int k = tid - 40;
        float s = 0.f;
        #pragma unroll
        for (int w = 0; w < 8; w++) s += sh_sc4[w][k];
        g_sb[n][bx][k] = s;
    }
}

// ---------------- K2: finalize ----------------
__global__ void __launch_bounds__(256) k_final(float* __restrict__ out) {
    __shared__ float  tot_s[N_IMG][2][C];
    __shared__ float  tot_c[N_IMG][2][C];
    __shared__ double s_g[4];
    __shared__ double s_img[N_IMG][2];
    const int tid  = threadIdx.x;
    const int lane = tid & 31;

    // phase 1a: reduce per-class partials over blocks (152 threads)
    if (tid < N_IMG * 2 * C) {
        const int n    = tid / (2 * C);
        const int r    = tid % (2 * C);
        const int kind = r / C;
        const int c    = r % C;
        const float* ps = kind ? &g_as[n][0][c] : &g_ss[n][0][c];
        const float* pcn = kind ? &g_ca[n][0][c] : &g_cs[n][0][c];
        float s = 0.f, cnt = 0.f;
        #pragma unroll 4
        for (int b = 0; b < MB; b++) { s += ps[b * C]; cnt += pcn[b * C]; }
        tot_s[n][kind][c] = s;
        tot_c[n][kind][c] = cnt;
    }
    // phase 1b: reduce BCE scalars (warp 6)
    if ((tid >> 5) == 6) {
        const int comp  = lane & 3;
        const int chunk = lane >> 2;
        double v = 0.0;
        for (int i = chunk; i < N_IMG * MB; i += 8)
            v += (double)((const float*)g_sb)[i * 4 + comp];
        #pragma unroll
        for (int o = 16; o >= 4; o >>= 1) v += __shfl_down_sync(0xffffffffu, v, o);
        if (lane < 4) s_g[comp] = v;
    }
    __syncthreads();

    // phase 2: per-image weights + dots (warp per image)
    const int n = tid >> 5;
    if (n < N_IMG) {
        #pragma unroll
        for (int kind = 0; kind < 2; kind++) {
            float cnt = (lane < C) ? tot_c[n][kind][lane] : 0.f;
            float ssm = (lane < C) ? tot_s[n][kind][lane] : 0.f;
            float total = cnt;
            #pragma unroll
            for (int o = 16; o > 0; o >>= 1) total += __shfl_xor_sync(0xffffffffu, total, o);
            float w = ((lane < C) && cnt != 0.f) ? (1.f - cnt / total) : 0.f;
            w += (lane < C) ? 1.f : 0.f;
            float num = -w * ssm;
            float den =  w * cnt;
            #pragma unroll
            for (int o = 16; o > 0; o >>= 1) {
                num += __shfl_down_sync(0xffffffffu, num, o);
                den += __shfl_down_sync(0xffffffffu, den, o);
            }
            if (lane == 0) s_img[n][kind] = (double)num / (double)den;
        }
    }
    __syncthreads();

    if (tid == 0) {
        const double sum  = s_g[0] + s_g[1];
        const double wpos = s_g[1] / sum;   // weight for t==1 pixels
        const double wneg = s_g[0] / sum;   // weight for t==0 pixels
        double loss = 0.3 * (wpos * s_g[2] + wneg * s_g[3]) / (double)(N_IMG * HW);
        #pragma unroll
        for (int i = 0; i < N_IMG; i++) {
            loss += 1.0 * s_img[i][0];   // SEG_W
            loss += 0.1 * s_img[i][1];   // ATT_W
        }
        out[0] = (float)loss;
    }
}

// ---------------- launch ----------------
extern "C" void kernel_launch(void* const* d_in, const int* in_sizes, int n_in,
                              void* d_out, int out_size) {
    const float* segin    = (const float*)d_in[0];
    const float* edgein   = (const float*)d_in[1];
    const int*   segmask  = (const int*)d_in[2];
    const int*   edgemask = (const int*)d_in[3];
    float* out = (float*)d_out;

    k_main<<<dim3(MB, N_IMG), 256>>>(segin, edgein, segmask, edgemask);
    k_final<<<1, 256>>>(out);
}

// round 7
// speedup vs baseline: 1.6921x; 1.6921x over previous
#include <cuda_runtime.h>

#define N_IMG 4
#define C 19
#define HH 768
#define WW 768
#define HW (HH * WW)
#define NV (HW / 4)
#define IGNORE_LBL 255
#define MB 288   // blocks per image

// ---------------- device accumulators (zeroed by k_zero each call) ----------------
__device__ double g_tsum[N_IMG][2][C];   // sum of lp by class: [kind 0=seg, 1=att]
__device__ double g_tcnt[N_IMG][2][C];   // counts by class (== histograms)
__device__ double g_g4[4];               // pos_cnt, neg_cnt, bce_pos, bce_neg

// ---------------- K0: zero accumulators ----------------
__global__ void k_zero() {
    const int tid = threadIdx.x;
    if (tid < N_IMG * 2 * C) {
        ((double*)g_tsum)[tid] = 0.0;
        ((double*)g_tcnt)[tid] = 0.0;
    }
    if (tid < 4) g_g4[tid] = 0.0;
}

// ---------------- K1: single fused streaming pass ----------------
__global__ void __launch_bounds__(256) k_main(const float* __restrict__ segin,
                                              const float* __restrict__ edgein,
                                              const int* __restrict__ segmask,
                                              const int* __restrict__ edgemask) {
    __shared__ float sh_ss[8][C], sh_cs[8][C], sh_as[8][C], sh_ca[8][C];
    __shared__ float sh_sc4[8][4];

    const int n    = blockIdx.y;
    const int bx   = blockIdx.x;
    const int tid  = threadIdx.x;
    const int wrp  = tid >> 5;
    const int lane = tid & 31;

    for (int i = tid; i < 8 * C; i += 256) {
        ((float*)sh_ss)[i] = 0.f; ((float*)sh_cs)[i] = 0.f;
        ((float*)sh_as)[i] = 0.f; ((float*)sh_ca)[i] = 0.f;
    }
    __syncthreads();

    const float4* sb4 = (const float4*)(segin    + (size_t)n * C * HW);
    const float4* ei4 = (const float4*)(edgein   + (size_t)n * HW);
    const int4*   sm4 = (const int4*)(segmask   + (size_t)n * HW);
    const int4*   em4 = (const int4*)(edgemask  + (size_t)n * HW);

    float pc = 0.f, nc = 0.f, sp = 0.f, sn = 0.f;

    const int stride = 256 * MB;
    for (int p = bx * 256 + tid; p < NV; p += stride) {
        const int4   t4 = sm4[p];
        const float4 e4 = ei4[p];
        const int4   m4 = em4[p];

        const int v0 = (t4.x != IGNORE_LBL), v1 = (t4.y != IGNORE_LBL),
                  v2 = (t4.z != IGNORE_LBL), v3 = (t4.w != IGNORE_LBL);
        const int tc0 = min(max(t4.x, 0), C - 1), tc1 = min(max(t4.y, 0), C - 1),
                  tc2 = min(max(t4.z, 0), C - 1), tc3 = min(max(t4.w, 0), C - 1);

        // O(1) logits: exp overflow-safe without max subtraction
        float s0 = 0.f, s1 = 0.f, s2 = 0.f, s3 = 0.f;
        float xt0 = 0.f, xt1 = 0.f, xt2 = 0.f, xt3 = 0.f;
        #pragma unroll
        for (int c = 0; c < C; c++) {
            float4 v = sb4[(size_t)c * NV + p];
            s0 += __expf(v.x); xt0 = (c == tc0) ? v.x : xt0;
            s1 += __expf(v.y); xt1 = (c == tc1) ? v.y : xt1;
            s2 += __expf(v.z); xt2 = (c == tc2) ? v.z : xt2;
            s3 += __expf(v.w); xt3 = (c == tc3) ? v.w : xt3;
        }
        const float lp0 = xt0 - __logf(s0);
        const float lp1 = xt1 - __logf(s1);
        const float lp2 = xt2 - __logf(s2);
        const float lp3 = xt3 - __logf(s3);

        // per-class accumulation (per-warp bins) + BCE scalar accumulation
        #pragma unroll
        for (int j = 0; j < 4; j++) {
            const int   vv = (j == 0) ? v0  : (j == 1) ? v1  : (j == 2) ? v2  : v3;
            const int   tc = (j == 0) ? tc0 : (j == 1) ? tc1 : (j == 2) ? tc2 : tc3;
            const float lp = (j == 0) ? lp0 : (j == 1) ? lp1 : (j == 2) ? lp2 : lp3;
            const float e  = (j == 0) ? e4.x : (j == 1) ? e4.y : (j == 2) ? e4.z : e4.w;
            const int   m  = (j == 0) ? m4.x : (j == 1) ? m4.y : (j == 2) ? m4.z : m4.w;

            if (vv) {
                atomicAdd(&sh_ss[wrp][tc], lp);
                atomicAdd(&sh_cs[wrp][tc], 1.f);
                if (e > 0.8f) {
                    atomicAdd(&sh_as[wrp][tc], lp);
                    atomicAdd(&sh_ca[wrp][tc], 1.f);
                }
            }

            const float b = fmaxf(e, 0.f) + __logf(1.f + __expf(-fabsf(e)));
            sp += (m == 1) ? (b - e) : 0.f;
            sn += (m == 0) ? b : 0.f;
            pc += (m == 1);
            nc += (m == 0);
        }
    }

    // scalar warp reduce
    #pragma unroll
    for (int o = 16; o > 0; o >>= 1) {
        pc += __shfl_down_sync(0xffffffffu, pc, o);
        nc += __shfl_down_sync(0xffffffffu, nc, o);
        sp += __shfl_down_sync(0xffffffffu, sp, o);
        sn += __shfl_down_sync(0xffffffffu, sn, o);
    }
    if (lane == 0) { sh_sc4[wrp][0] = pc; sh_sc4[wrp][1] = nc; sh_sc4[wrp][2] = sp; sh_sc4[wrp][3] = sn; }
    __syncthreads();

    // combine 8 warp bins -> direct global double atomics (308 addresses chip-wide)
    if (tid < 2 * C) {
        const int c    = tid % C;
        const int kind = tid / C;
        float s = 0.f, cnt = 0.f;
        #pragma unroll
        for (int w = 0; w < 8; w++) {
            s   += kind ? sh_as[w][c] : sh_ss[w][c];
            cnt += kind ? sh_ca[w][c] : sh_cs[w][c];
        }
        atomicAdd(&g_tsum[n][kind][c], (double)s);
        atomicAdd(&g_tcnt[n][kind][c], (double)cnt);
    }
    if (tid >= 64 && tid < 68) {
        const int k = tid - 64;
        float s = 0.f;
        #pragma unroll
        for (int w = 0; w < 8; w++) s += sh_sc4[w][k];
        atomicAdd(&g_g4[k], (double)s);
    }
}

// ---------------- K2: finalize (tiny: 308 doubles in, 1 float out) ----------------
__global__ void __launch_bounds__(128) k_final(float* __restrict__ out) {
    __shared__ double s_img[N_IMG][2];
    const int tid  = threadIdx.x;
    const int lane = tid & 31;
    const int n    = tid >> 5;   // warp per image

    if (n < N_IMG) {
        #pragma unroll
        for (int kind = 0; kind < 2; kind++) {
            double cnt = (lane < C) ? g_tcnt[n][kind][lane] : 0.0;
            double ssm = (lane < C) ? g_tsum[n][kind][lane] : 0.0;
            double total = cnt;
            #pragma unroll
            for (int o = 16; o > 0; o >>= 1) total += __shfl_xor_sync(0xffffffffu, total, o);
            double w = ((lane < C) && cnt != 0.0) ? (1.0 - cnt / total) : 0.0;
            w += (lane < C) ? 1.0 : 0.0;
            double num = -w * ssm;
            double den =  w * cnt;
            #pragma unroll
            for (int o = 16; o > 0; o >>= 1) {
                num += __shfl_down_sync(0xffffffffu, num, o);
                den += __shfl_down_sync(0xffffffffu, den, o);
            }
            if (lane == 0) s_img[n][kind] = num / den;
        }
    }
    __syncthreads();

    if (tid == 0) {
        const double p = g_g4[0], q = g_g4[1];
        const double sum  = p + q;
        const double wpos = q / sum;   // weight for t==1 pixels
        const double wneg = p / sum;   // weight for t==0 pixels
        double loss = 0.3 * (wpos * g_g4[2] + wneg * g_g4[3]) / (double)(N_IMG * HW);
        #pragma unroll
        for (int i = 0; i < N_IMG; i++) {
            loss += 1.0 * s_img[i][0];   // SEG_W
            loss += 0.1 * s_img[i][1];   // ATT_W
        }
        out[0] = (float)loss;
    }
}

// ---------------- launch ----------------
extern "C" void kernel_launch(void* const* d_in, const int* in_sizes, int n_in,
                              void* d_out, int out_size) {
    const float* segin    = (const float*)d_in[0];
    const float* edgein   = (const float*)d_in[1];
    const int*   segmask  = (const int*)d_in[2];
    const int*   edgemask = (const int*)d_in[3];
    float* out = (float*)d_out;

    k_zero<<<1, 256>>>();
    k_main<<<dim3(MB, N_IMG), 256>>>(segin, edgein, segmask, edgemask);
    k_final<<<1, 128>>>(out);
}